// round 8
// baseline (speedup 1.0000x reference)
#include <cuda_runtime.h>
#include <cuda_bf16.h>
#include <cstdint>

// ---------------------------------------------------------------------------
// LSTM: batch=64, seq=512, input=512, hidden=512, fp32.
// Inputs: x [64,512,512], weight_ih [2048,512], weight_hh [2048,512],
//         bias_ih [2048], bias_hh [2048].
// Output: hidden_seq [64,512,512], h_f [64,512], c_f [64,512].
// ---------------------------------------------------------------------------

#define BATCH 64
#define SEQ   512
#define ISZ   512
#define HS    512
#define GATES (4 * HS)   // 2048

__device__ float g_xproj[(size_t)SEQ * BATCH * GATES];   // 256 MB scratch
__device__ float g_h[2][HS][BATCH];                      // transposed h, double buffer
__device__ __align__(16) unsigned g_flags[128];          // per-block progress flags

// ---------------- packed f32x2 helpers ----------------
__device__ __forceinline__ unsigned long long bcast2(float x) {
    unsigned long long r; unsigned u = __float_as_uint(x);
    asm("mov.b64 %0, {%1, %1};" : "=l"(r) : "r"(u));
    return r;
}
__device__ __forceinline__ void fma2(unsigned long long &acc,
                                     unsigned long long a, unsigned long long b) {
    asm("fma.rn.f32x2 %0, %1, %2, %0;" : "+l"(acc) : "l"(a), "l"(b));
}
__device__ __forceinline__ float2 unpack2(unsigned long long v) {
    unsigned lo, hi;
    asm("mov.b64 {%0, %1}, %2;" : "=r"(lo), "=r"(hi) : "l"(v));
    return make_float2(__uint_as_float(lo), __uint_as_float(hi));
}

// ===========================================================================
// Kernel 1: x_proj GEMM, 128x128x8 tile, f32x2 packed math.
// Block (0,0) also resets the progress flags (stream-ordered before kernel 2).
// ===========================================================================
#define GBM 128
#define GBN 128
#define GBK 8

__global__ __launch_bounds__(256, 2)
void xproj_gemm_kernel(const float* __restrict__ x,
                       const float* __restrict__ wih,
                       const float* __restrict__ bih,
                       const float* __restrict__ bhh)
{
    if (blockIdx.x == 0 && blockIdx.y == 0 && threadIdx.x < 128)
        g_flags[threadIdx.x] = 0u;

    __shared__ float As[GBK][GBM];
    __shared__ float Bs[GBK][GBN];

    const int tid = threadIdx.x;
    const int m0 = blockIdx.y * GBM;
    const int n0 = blockIdx.x * GBN;

    const int lrow = tid >> 1;
    const int lk4  = (tid & 1) * 4;

    const int tx = tid & 15;
    const int ty = tid >> 4;

    unsigned long long acc2[8][4];
#pragma unroll
    for (int i = 0; i < 8; i++)
#pragma unroll
        for (int j2 = 0; j2 < 4; j2++) acc2[i][j2] = 0ull;

    const float* Aptr = x   + (size_t)(m0 + lrow) * ISZ + lk4;
    const float* Bptr = wih + (size_t)(n0 + lrow) * ISZ + lk4;

    float4 pa = *(const float4*)Aptr;
    float4 pb = *(const float4*)Bptr;

    const int NTK = ISZ / GBK;
    for (int t = 0; t < NTK; t++) {
        As[lk4 + 0][lrow] = pa.x; As[lk4 + 1][lrow] = pa.y;
        As[lk4 + 2][lrow] = pa.z; As[lk4 + 3][lrow] = pa.w;
        Bs[lk4 + 0][lrow] = pb.x; Bs[lk4 + 1][lrow] = pb.y;
        Bs[lk4 + 2][lrow] = pb.z; Bs[lk4 + 3][lrow] = pb.w;
        __syncthreads();

        if (t + 1 < NTK) {
            pa = *(const float4*)(Aptr + (t + 1) * GBK);
            pb = *(const float4*)(Bptr + (t + 1) * GBK);
        }

#pragma unroll
        for (int kk = 0; kk < GBK; kk++) {
            unsigned long long a2[8], b2[4];
#pragma unroll
            for (int i = 0; i < 8; i++) a2[i] = bcast2(As[kk][ty * 8 + i]);
#pragma unroll
            for (int j2 = 0; j2 < 4; j2++)
                b2[j2] = *(const unsigned long long*)&Bs[kk][tx * 8 + j2 * 2];
#pragma unroll
            for (int i = 0; i < 8; i++)
#pragma unroll
                for (int j2 = 0; j2 < 4; j2++)
                    fma2(acc2[i][j2], a2[i], b2[j2]);
        }
        __syncthreads();
    }

    float bsum[8];
#pragma unroll
    for (int j = 0; j < 8; j++) {
        int n = n0 + tx * 8 + j;
        bsum[j] = bih[n] + bhh[n];
    }

#pragma unroll
    for (int i = 0; i < 8; i++) {
        int m = m0 + ty * 8 + i;
        int b = m >> 9;
        int s = m & 511;
        float* orow = g_xproj + ((size_t)s * BATCH + b) * GATES + n0 + tx * 8;
#pragma unroll
        for (int j2 = 0; j2 < 4; j2 += 2) {
            float2 f0 = unpack2(acc2[i][j2 + 0]);
            float2 f1 = unpack2(acc2[i][j2 + 1]);
            float4 v;
            v.x = f0.x + bsum[j2 * 2 + 0];
            v.y = f0.y + bsum[j2 * 2 + 1];
            v.z = f1.x + bsum[j2 * 2 + 2];
            v.w = f1.y + bsum[j2 * 2 + 3];
            *(float4*)(orow + j2 * 2) = v;
        }
    }
}

// ===========================================================================
// Kernel 2: persistent recurrence. Round-5 compute structure (conflict-free
// LDS mapping), flag-array synchronization instead of atomic grid barrier.
// 128 blocks (1/SM), 512 threads. Block owns 4 hidden units (16 W rows),
// all 64 batches. W_hh resident in smem; c state in registers.
// ===========================================================================
#define NB   128
#define NT   512
#define WSTR 520                 // padded W row stride (2080 B, 16B-aligned)
#define HTR  68                  // padded h row stride (272 B, 16B-aligned)
#define SMW  (16 * WSTR)         // 8320 floats
#define SMH  (HS * HTR)          // 34816 floats
#define SMRED (16 * 4 * 4 * 8)   // 2048 floats
#define PERS_SMEM_BYTES ((SMW + SMH + SMRED) * 4)   // 180,736 B

__device__ __forceinline__ float fsigmoid(float x) {
    return 1.f / (1.f + __expf(-x));
}
__device__ __forceinline__ float ftanh_fast(float x) {
    return 2.f / (1.f + __expf(-2.f * x)) - 1.f;
}

__device__ __forceinline__ uint4 ld_volatile_u4(const unsigned* p) {
    uint4 v;
    asm volatile("ld.volatile.global.v4.u32 {%0,%1,%2,%3}, [%4];"
                 : "=r"(v.x), "=r"(v.y), "=r"(v.z), "=r"(v.w) : "l"(p));
    return v;
}

__global__ __launch_bounds__(NT, 1)
void lstm_persistent_kernel(const float* __restrict__ whh,
                            float* __restrict__ out,
                            float* __restrict__ hf_out,
                            float* __restrict__ cf_out)
{
    extern __shared__ float sm[];
    float* W_s = sm;                 // [16][WSTR], row = g*4 + jl
    float* h_s = sm + SMW;           // [512][HTR], [k][b]
    float* red = sm + SMW + SMH;     // [16][4][4][8]

    const int tid = threadIdx.x;
    const int bid = blockIdx.x;
    const int j0 = bid * 4;

    // ---- stage W_hh once for the whole sequence ----
    for (int t = tid; t < 16 * 128; t += NT) {
        int row = t >> 7;
        int kq = (t & 127) << 2;
        int g = row >> 2, jl = row & 3;
        float4 v = *(const float4*)(whh + (size_t)(g * HS + j0 + jl) * HS + kq);
        *(float4*)&W_s[row * WSTR + kq] = v;
    }
    __syncthreads();

    const int jl   = tid & 3;            // gate column within block
    const int ksub = (tid >> 2) & 15;    // k slice
    const int bg   = tid >> 6;           // batch group (8 batches)
    const int b0   = bg * 8;
    const int warp = tid >> 5;
    const int lane = tid & 31;

    // cell-update mapping (threads 0..255)
    const int ub = tid >> 2;             // batch
    const int uj = j0 + (tid & 3);       // hidden unit
    float c_reg = 0.f;

    for (int s = 0; s < SEQ; s++) {
        // prefetch x_proj early (issues before the flag poll, hides DRAM)
        float xp0 = 0.f, xp1 = 0.f, xp2 = 0.f, xp3 = 0.f;
        if (tid < 256) {
            const float* xp = g_xproj + ((size_t)s * BATCH + ub) * GATES;
            xp0 = xp[0 * HS + uj];
            xp1 = xp[1 * HS + uj];
            xp2 = xp[2 * HS + uj];
            xp3 = xp[3 * HS + uj];
        }

        float gsum[4] = {0.f, 0.f, 0.f, 0.f};

        if (s > 0) {
            // ---- wait until all blocks finished step s-1 (flags >= s) ----
            if (tid < 32) {
                const unsigned target = (unsigned)s;
                for (;;) {
                    uint4 f = ld_volatile_u4(&g_flags[tid * 4]);
                    unsigned mn = min(min(f.x, f.y), min(f.z, f.w));
                    if (__all_sync(0xffffffffu, mn >= target)) break;
                }
                __threadfence();   // acquire side (cumulative)
            }
            __syncthreads();

            // ---- stage h_{s-1}: g_h[(s-1)&1][k][b] -> h_s ----
            const float* hsrc = &g_h[(s + 1) & 1][0][0];
            for (int t = tid; t < (HS * BATCH) / 4; t += NT) {
                int k  = t >> 4;
                int c4 = (t & 15) << 2;
                float4 v = *(const float4*)(hsrc + k * BATCH + c4);
                *(float4*)&h_s[k * HTR + c4] = v;
            }
            __syncthreads();

            // ---- packed dot products: 4 gates x 8 batches (4 pairs) x 32 k ----
            unsigned long long acc[4][4];
#pragma unroll
            for (int pi = 0; pi < 4; pi++)
#pragma unroll
                for (int g = 0; g < 4; g++) acc[pi][g] = 0ull;

#pragma unroll 4
            for (int r = 0; r < 32; r++) {
                int k = ksub + (r << 4);
                unsigned long long w2[4];
#pragma unroll
                for (int g = 0; g < 4; g++)
                    w2[g] = bcast2(W_s[(g * 4 + jl) * WSTR + k]);
                const float* hrow = &h_s[k * HTR + b0];
#pragma unroll
                for (int pi = 0; pi < 4; pi++) {
                    unsigned long long h2 = *(const unsigned long long*)(hrow + pi * 2);
#pragma unroll
                    for (int g = 0; g < 4; g++) fma2(acc[pi][g], h2, w2[g]);
                }
            }

            // ---- butterfly over ksub low 3 bits (lane bits 2..4) ----
            float v[4][4][2];
#pragma unroll
            for (int pi = 0; pi < 4; pi++)
#pragma unroll
                for (int g = 0; g < 4; g++) {
                    float2 f = unpack2(acc[pi][g]);
                    v[pi][g][0] = f.x; v[pi][g][1] = f.y;
                }
#pragma unroll
            for (int off = 4; off <= 16; off <<= 1) {
#pragma unroll
                for (int pi = 0; pi < 4; pi++)
#pragma unroll
                    for (int g = 0; g < 4; g++) {
                        v[pi][g][0] += __shfl_xor_sync(0xffffffffu, v[pi][g][0], off);
                        v[pi][g][1] += __shfl_xor_sync(0xffffffffu, v[pi][g][1], off);
                    }
            }
            if (lane < 4) {   // lane == jl representative
#pragma unroll
                for (int pi = 0; pi < 4; pi++)
#pragma unroll
                    for (int g = 0; g < 4; g++) {
                        red[((warp * 4 + lane) * 4 + pi) * 8 + g * 2 + 0] = v[pi][g][0];
                        red[((warp * 4 + lane) * 4 + pi) * 8 + g * 2 + 1] = v[pi][g][1];
                    }
            }
            __syncthreads();

            if (tid < 256) {
                int cbg = ub >> 3;
                int cpi = (ub & 7) >> 1;
                int cel = ub & 1;
                int cjl = tid & 3;
                int w0 = cbg * 2, w1 = cbg * 2 + 1;
#pragma unroll
                for (int g = 0; g < 4; g++)
                    gsum[g] = red[((w0 * 4 + cjl) * 4 + cpi) * 8 + g * 2 + cel]
                            + red[((w1 * 4 + cjl) * 4 + cpi) * 8 + g * 2 + cel];
            }
        }

        // ---- cell update ----
        if (tid < 256) {
            float gi = gsum[0] + xp0;
            float gf = gsum[1] + xp1;
            float gc = gsum[2] + xp2;
            float go = gsum[3] + xp3;

            float i_ = fsigmoid(gi);
            float f_ = fsigmoid(gf);
            float g_ = ftanh_fast(gc);
            float o_ = fsigmoid(go);

            float cn = f_ * c_reg + i_ * g_;
            float hn = o_ * ftanh_fast(cn);
            c_reg = cn;

            out[((size_t)ub * SEQ + s) * HS + uj] = hn;
            g_h[s & 1][uj][ub] = hn;
            if (s == SEQ - 1 && hf_out != nullptr) {
                hf_out[ub * HS + uj] = hn;
                cf_out[ub * HS + uj] = cn;
            }
        }

        // ---- publish progress: fire-and-forget flag (no wait here) ----
        __syncthreads();
        if (tid == 0) {
            __threadfence();   // make h writes visible (cumulative release)
            *(volatile unsigned*)&g_flags[bid] = (unsigned)(s + 1);
        }
    }
}

// ===========================================================================
// Launch
// ===========================================================================
extern "C" void kernel_launch(void* const* d_in, const int* in_sizes, int n_in,
                              void* d_out, int out_size)
{
    const float* x   = (const float*)d_in[0];
    const float* wih = (const float*)d_in[1];
    const float* whh = (const float*)d_in[2];
    const float* bih = (const float*)d_in[3];
    const float* bhh = (const float*)d_in[4];

    float* out = (float*)d_out;

    const size_t hidden_elems = (size_t)BATCH * SEQ * HS;
    float* hf = nullptr;
    float* cf = nullptr;
    if ((size_t)out_size >= hidden_elems + 2 * (size_t)BATCH * HS) {
        hf = out + hidden_elems;
        cf = hf + (size_t)BATCH * HS;
    }

    cudaFuncSetAttribute(lstm_persistent_kernel,
                         cudaFuncAttributeMaxDynamicSharedMemorySize,
                         PERS_SMEM_BYTES);

    // Phase 1: input projection GEMM (also resets progress flags)
    dim3 ggrid(GATES / GBN, (BATCH * SEQ) / GBM);
    xproj_gemm_kernel<<<ggrid, 256>>>(x, wih, bih, bhh);

    // Phase 2: persistent recurrence (single launch, flag-array sync)
    lstm_persistent_kernel<<<NB, NT, PERS_SMEM_BYTES>>>(whh, out, hf, cf);
}